// round 15
// baseline (speedup 1.0000x reference)
#include <cuda_runtime.h>

// PatchChamferDistance: B=32, G=64, P=256, D=3 (fp32)
// R15 = R14 joint scan (each pair ONCE) with 2 columns per iteration:
// 8 independent fma2 chains in flight (was 4) to cover LDS/fma latency.
// lane rg owns rows [8rg,8rg+8); warp cg owns cols [32cg,32cg+32).
// t_ij = d2_ij + C; rowmin in regs; colmin = 8-row tree + one xor-1
// shuffle + STS to colsm[warp][col][16]; epilogue finishes both mins.

#define BGQ  2048
#define NP   256
#define T    256
#define BIAS 128.0f
#define POSINF_BITS 0x7F800000

typedef unsigned long long u64;

__device__ float    g_accum;
__device__ unsigned g_count;

__device__ __forceinline__ u64 pk2(float a, float b) {
    u64 r;
    asm("mov.b64 %0, {%1, %2};" : "=l"(r) : "f"(a), "f"(b));
    return r;
}
__device__ __forceinline__ u64 fma2(u64 a, u64 b, u64 c) {
    u64 d;
    asm("fma.rn.f32x2 %0, %1, %2, %3;" : "=l"(d) : "l"(a), "l"(b), "l"(c));
    return d;
}
__device__ __forceinline__ u64 add2(u64 a, u64 b) {
    u64 d;
    asm("add.rn.f32x2 %0, %1, %2;" : "=l"(d) : "l"(a), "l"(b));
    return d;
}
__device__ __forceinline__ void upk2i(u64 v, int& lo, int& hi) {
    asm("mov.b64 {%0, %1}, %2;" : "=r"(lo), "=r"(hi) : "l"(v));
}

__global__ __launch_bounds__(T)
void pcd_chamfer_kernel(const float* __restrict__ pred,
                        const float* __restrict__ tgt,
                        float* __restrict__ out)
{
    __shared__ float4     srow[NP];          // pred rows {x,y,z,w}
    __shared__ ulonglong2 scA[NP];           // tgt: {-2x,-2x,-2y,-2y}
    __shared__ ulonglong2 scB[NP];           // tgt: {-2z,-2z, w+C, w+C}
    __shared__ int        colsm[8][32][20];  // [warp][col][16 slots + pad]
    __shared__ int        rowpart[8][NP];    // per-warp rowmin partials
    __shared__ float      wsum[T / 32];

    const int t     = threadIdx.x;
    const int patch = blockIdx.x;

    const float* pb = pred + (size_t)patch * NP * 3;
    const float* qb = tgt  + (size_t)patch * NP * 3;

    // phase 1: cooperative load, 1 point of each cloud per thread
    {
        float x = pb[t * 3 + 0], y = pb[t * 3 + 1], z = pb[t * 3 + 2];
        srow[t] = make_float4(x, y, z, x * x + y * y + z * z);

        x = qb[t * 3 + 0]; y = qb[t * 3 + 1]; z = qb[t * 3 + 2];
        float w = x * x + y * y + z * z;
        scA[t] = make_ulonglong2(pk2(-2.f * x, -2.f * x), pk2(-2.f * y, -2.f * y));
        scB[t] = make_ulonglong2(pk2(-2.f * z, -2.f * z), pk2(w + BIAS, w + BIAS));
    }
    __syncthreads();

    const int rg = t & 31;     // lane -> rows [8rg, 8rg+8)
    const int cg = t >> 5;     // warp -> cols [32cg, 32cg+32)

    // own 8 pred rows, packed pairwise
    u64 X2[4], Y2[4], Z2[4], W2[4];
#pragma unroll
    for (int k = 0; k < 4; k++) {
        float4 r0 = srow[8 * rg + 2 * k];
        float4 r1 = srow[8 * rg + 2 * k + 1];
        X2[k] = pk2(r0.x, r1.x);
        Y2[k] = pk2(r0.y, r1.y);
        Z2[k] = pk2(r0.z, r1.z);
        W2[k] = pk2(r0.w, r1.w);   // {pw0, pw1}
    }

    int rmn[8];
#pragma unroll
    for (int r = 0; r < 8; r++) rmn[r] = POSINF_BITS;

    const int c0 = cg * 32;

#pragma unroll 2
    for (int jj = 0; jj < 16; jj++) {
        const int j0 = c0 + 2 * jj;
        ulonglong2 a0 = scA[j0];       // warp-uniform -> LDS broadcast
        ulonglong2 b0 = scB[j0];
        ulonglong2 a1 = scA[j0 + 1];
        ulonglong2 b1 = scB[j0 + 1];

        // 8 independent chains: t = {pw + qw + C - 2 dot} = {d2 + C} > 0
        int d0[8], d1[8];
#pragma unroll
        for (int k = 0; k < 4; k++) {
            u64 s0 = add2(W2[k], b0.y);
            u64 s1 = add2(W2[k], b1.y);
            u64 acc0 = fma2(X2[k], a0.x, s0);
            u64 acc1 = fma2(X2[k], a1.x, s1);
            acc0 = fma2(Y2[k], a0.y, acc0);
            acc1 = fma2(Y2[k], a1.y, acc1);
            acc0 = fma2(Z2[k], b0.x, acc0);
            acc1 = fma2(Z2[k], b1.x, acc1);
            upk2i(acc0, d0[2 * k], d0[2 * k + 1]);
            upk2i(acc1, d1[2 * k], d1[2 * k + 1]);
        }

        // rowmin updates (16 IMNMX, alu)
#pragma unroll
        for (int r = 0; r < 8; r++)
            rmn[r] = min(rmn[r], min(d0[r], d1[r]));

        // colmin trees over own 8 rows (7 IMNMX each)
        int m0 = min(min(min(d0[0], d0[1]), min(d0[2], d0[3])),
                     min(min(d0[4], d0[5]), min(d0[6], d0[7])));
        int m1 = min(min(min(d1[0], d1[1]), min(d1[2], d1[3])),
                     min(min(d1[4], d1[5]), min(d1[6], d1[7])));
        // one xor-1 stage each (32 -> 16 partials), then straight to smem
        m0 = min(m0, __shfl_xor_sync(0xffffffffu, m0, 1));
        m1 = min(m1, __shfl_xor_sync(0xffffffffu, m1, 1));
        colsm[cg][2 * jj][rg >> 1]     = m0;   // dup-pair writes: benign
        colsm[cg][2 * jj + 1][rg >> 1] = m1;
    }

    // rowmin partials -> smem
#pragma unroll
    for (int r = 0; r < 8; r++)
        rowpart[cg][8 * rg + r] = rmn[r];
    __syncthreads();

    // ---- epilogue: finish both mins, once per thread ----
    float v = 0.f;
    {   // column t: min of its 16 smem partials
        const int* cp = colsm[t >> 5][t & 31];
        int m = cp[0];
#pragma unroll
        for (int i = 1; i < 16; i++) m = min(m, cp[i]);
        v += fmaxf(__int_as_float(m) - BIAS, 0.f);
    }
    {   // row t: min across the 8 warps' partials
        int m = rowpart[0][t];
#pragma unroll
        for (int w = 1; w < 8; w++) m = min(m, rowpart[w][t]);
        v += fmaxf(__int_as_float(m) - BIAS, 0.f);
    }

    // block reduction
#pragma unroll
    for (int o = 16; o > 0; o >>= 1)
        v += __shfl_down_sync(0xffffffffu, v, o);
    if ((t & 31) == 0) wsum[t >> 5] = v;
    __syncthreads();

    // last-CTA pattern: single launch, no zero kernel
    if (t == 0) {
        float s = 0.f;
#pragma unroll
        for (int w = 0; w < T / 32; w++) s += wsum[w];
        atomicAdd(&g_accum, s);
        __threadfence();
        unsigned done = atomicAdd(&g_count, 1u);
        if (done == (unsigned)(gridDim.x - 1)) {
            __threadfence();
            float total = *((volatile float*)&g_accum);
            out[0] = total * (1.0f / ((float)NP * (float)BGQ));
            g_accum = 0.f;
            __threadfence();
            g_count = 0u;
        }
    }
}

extern "C" void kernel_launch(void* const* d_in, const int* in_sizes, int n_in,
                              void* d_out, int out_size)
{
    const float* pred = (const float*)d_in[0];
    const float* tgt  = (const float*)d_in[1];
    float* out = (float*)d_out;

    pcd_chamfer_kernel<<<BGQ, T>>>(pred, tgt, out);
}